// round 2
// baseline (speedup 1.0000x reference)
#include <cuda_runtime.h>

// IF spiking neuron forward: T=8 scan, soft reset, spike = thresh * (mem >= thresh).
// x: [T*B, C, H, W] f32 (T=8, timestep stride = total/8 elements), thresh: [1] f32.
// Per neuron: mem = 0.5*thr; for t: m = mem + x[t]; sp = (m>=thr)?thr:0; out[t]=sp; mem = m-sp.
//
// Pure HBM-streaming problem (256 MiB traffic, zero reuse). Strategy:
//  - one thread per float4 of neurons, all 8 timestep loads front-batched (MLP=8)
//  - persistent grid-stride: 1024 blocks x 256 thr = 2^18 threads; n_vec = 2^20
//    -> exactly 4 iterations/thread, single resident wave, no wave transitions
//  - __ldcs/__stcs evict-first hints: no reuse, keep L2 turnaround clean
//  - spikes written back into the load registers to stay at <=32 regs (occ 8)

#ifndef IF_T
#define IF_T 8
#endif

__global__ __launch_bounds__(256, 8)
void if_scan_kernel(const float4* __restrict__ x,
                    const float* __restrict__ thresh,
                    float4* __restrict__ out,
                    int n_vec, int stride_vec)
{
    const float thr = __ldg(thresh);
    const float half_thr = 0.5f * thr;
    const int step = gridDim.x * blockDim.x;

    for (int n = blockIdx.x * blockDim.x + threadIdx.x; n < n_vec; n += step) {
        // Front-batch all T independent loads (128B in flight per thread)
        float4 v[IF_T];
#pragma unroll
        for (int t = 0; t < IF_T; ++t)
            v[t] = __ldcs(&x[(size_t)t * stride_vec + n]);

        float mx = half_thr, my = half_thr, mz = half_thr, mw = half_thr;

#pragma unroll
        for (int t = 0; t < IF_T; ++t) {
            mx += v[t].x; my += v[t].y; mz += v[t].z; mw += v[t].w;
            float sx = (mx >= thr) ? thr : 0.0f;
            float sy = (my >= thr) ? thr : 0.0f;
            float sz = (mz >= thr) ? thr : 0.0f;
            float sw = (mw >= thr) ? thr : 0.0f;
            v[t].x = sx; v[t].y = sy; v[t].z = sz; v[t].w = sw;  // reuse regs
            mx -= sx; my -= sy; mz -= sz; mw -= sw;
        }

#pragma unroll
        for (int t = 0; t < IF_T; ++t)
            __stcs(&out[(size_t)t * stride_vec + n], v[t]);
    }
}

extern "C" void kernel_launch(void* const* d_in, const int* in_sizes, int n_in,
                              void* d_out, int out_size)
{
    const float* x      = (const float*)d_in[0];
    const float* thresh = (const float*)d_in[1];
    float* out          = (float*)d_out;

    const int total = in_sizes[0];          // T*B*C*H*W = 33,554,432
    const int stride = total / IF_T;        // per-timestep elements = 4,194,304
    const int stride_vec = stride / 4;      // float4 units = 1,048,576
    const int n_vec = stride_vec;

    const int threads = 256;
    // Single resident wave; n_vec = 2^20 -> exactly 4 grid-stride iterations/thread.
    int blocks = 1024;
    const int needed = (n_vec + threads - 1) / threads;
    if (blocks > needed) blocks = needed;

    if_scan_kernel<<<blocks, threads>>>((const float4*)x, thresh,
                                        (float4*)out, n_vec, stride_vec);
}

// round 3
// speedup vs baseline: 1.1677x; 1.1677x over previous
#include <cuda_runtime.h>

// IF spiking neuron forward: T=8 scan, soft reset, spike = thresh * (mem >= thresh).
// x: [T*B, C, H, W] f32 (T=8, timestep stride = total/8 elements), thresh: [1] f32.
// Per neuron: mem = 0.5*thr; for t: m = mem + x[t]; sp = (m>=thr)?thr:0; out[t]=sp; mem=m-sp.
//
// Pure HBM-streaming (256 MiB traffic, zero reuse). R1 post-mortem: persistent
// grid-stride LOSES to one-shot multi-wave launch (fresh CTAs keep SM-wide MLP
// saturated; grid-stride loop-carried WAR chain + 4x fewer threads starved DRAM).
// So: R0 structure (4096 blocks x 256 thr, one float4/thread, exact cover) plus
// evict-first .cs hints on the streamed loads and stores.

#ifndef IF_T
#define IF_T 8
#endif

__global__ __launch_bounds__(256, 8)
void if_scan_kernel(const float4* __restrict__ x,
                    const float* __restrict__ thresh,
                    float4* __restrict__ out,
                    int stride_vec)
{
    const int n = blockIdx.x * blockDim.x + threadIdx.x;  // exact cover: grid*block == n_vec

    const float thr = __ldg(thresh);

    // Front-batch all T independent loads (MLP=8, 128B in flight per thread)
    float4 v[IF_T];
#pragma unroll
    for (int t = 0; t < IF_T; ++t)
        v[t] = __ldcs(&x[(size_t)t * stride_vec + n]);

    float mx = 0.5f * thr, my = 0.5f * thr, mz = 0.5f * thr, mw = 0.5f * thr;

#pragma unroll
    for (int t = 0; t < IF_T; ++t) {
        mx += v[t].x; my += v[t].y; mz += v[t].z; mw += v[t].w;
        float sx = (mx >= thr) ? thr : 0.0f;
        float sy = (my >= thr) ? thr : 0.0f;
        float sz = (mz >= thr) ? thr : 0.0f;
        float sw = (mw >= thr) ? thr : 0.0f;
        v[t].x = sx; v[t].y = sy; v[t].z = sz; v[t].w = sw;  // reuse regs for spikes
        mx -= sx; my -= sy; mz -= sz; mw -= sw;
    }

#pragma unroll
    for (int t = 0; t < IF_T; ++t)
        __stcs(&out[(size_t)t * stride_vec + n], v[t]);
}

extern "C" void kernel_launch(void* const* d_in, const int* in_sizes, int n_in,
                              void* d_out, int out_size)
{
    const float* x      = (const float*)d_in[0];
    const float* thresh = (const float*)d_in[1];
    float* out          = (float*)d_out;

    const int total = in_sizes[0];          // T*B*C*H*W = 33,554,432
    const int stride = total / IF_T;        // per-timestep elements = 4,194,304
    const int stride_vec = stride / 4;      // float4 units = 1,048,576 = 2^20

    const int threads = 256;
    const int blocks = stride_vec / threads;  // 4096, exact cover

    if_scan_kernel<<<blocks, threads>>>((const float4*)x, thresh,
                                        (float4*)out, stride_vec);
}

// round 4
// speedup vs baseline: 1.2388x; 1.0609x over previous
#include <cuda_runtime.h>

// IF spiking neuron forward: T=8 scan, soft reset, spike = thresh * (mem >= thresh).
// x: [T*B, C, H, W] f32 (T=8, timestep stride = total/8 elements), thresh: [1] f32.
// Per neuron: mem = 0.5*thr; for t: m = mem + x[t]; sp = (m>=thr)?thr:0; out[t]=sp; mem=m-sp.
//
// Pure HBM-streaming (268 MB traffic, zero reuse). Findings so far:
//   R0: one-shot 4096x256, plain LDG/STG, front-batched loads  -> 37.5us ncu (best)
//   R1: persistent grid-stride -> 53.6us (SM-wide MLP collapse; REJECTED)
//   R2: .cs evict-first hints  -> 45.6us (L1tex path overhead;  REJECTED)
// R3: R0 structure, plain caching, CTA shape 512x2048 (same 64 warps/SM, fewer
// CTA boundaries per wave), exact cover, no bounds guard.

#ifndef IF_T
#define IF_T 8
#endif

__global__ __launch_bounds__(512, 4)
void if_scan_kernel(const float4* __restrict__ x,
                    const float* __restrict__ thresh,
                    float4* __restrict__ out,
                    int stride_vec)
{
    const int n = blockIdx.x * blockDim.x + threadIdx.x;  // exact cover: grid*block == n_vec

    const float thr = __ldg(thresh);

    // Front-batch all T independent loads (MLP=8, 128B in flight per thread)
    float4 v[IF_T];
#pragma unroll
    for (int t = 0; t < IF_T; ++t)
        v[t] = x[(size_t)t * stride_vec + n];

    float mx = 0.5f * thr, my = 0.5f * thr, mz = 0.5f * thr, mw = 0.5f * thr;

#pragma unroll
    for (int t = 0; t < IF_T; ++t) {
        mx += v[t].x; my += v[t].y; mz += v[t].z; mw += v[t].w;
        float sx = (mx >= thr) ? thr : 0.0f;
        float sy = (my >= thr) ? thr : 0.0f;
        float sz = (mz >= thr) ? thr : 0.0f;
        float sw = (mw >= thr) ? thr : 0.0f;
        v[t].x = sx; v[t].y = sy; v[t].z = sz; v[t].w = sw;  // reuse regs for spikes
        mx -= sx; my -= sy; mz -= sz; mw -= sw;
    }

#pragma unroll
    for (int t = 0; t < IF_T; ++t)
        out[(size_t)t * stride_vec + n] = v[t];
}

extern "C" void kernel_launch(void* const* d_in, const int* in_sizes, int n_in,
                              void* d_out, int out_size)
{
    const float* x      = (const float*)d_in[0];
    const float* thresh = (const float*)d_in[1];
    float* out          = (float*)d_out;

    const int total = in_sizes[0];          // T*B*C*H*W = 33,554,432
    const int stride = total / IF_T;        // per-timestep elements = 4,194,304
    const int stride_vec = stride / 4;      // float4 units = 1,048,576 = 2^20

    const int threads = 512;
    const int blocks = stride_vec / threads;  // 2048, exact cover

    if_scan_kernel<<<blocks, threads>>>((const float4*)x, thresh,
                                        (float4*)out, stride_vec);
}

// round 6
// speedup vs baseline: 1.2397x; 1.0007x over previous
#include <cuda_runtime.h>

// IF spiking neuron forward: T=8 scan, soft reset, spike = thresh * (mem >= thresh).
// x: [T*B, C, H, W] f32 (T=8, timestep stride = total/8 elements), thresh: [1] f32.
// Per neuron: mem = 0.5*thr; for t: m = mem + x[t]; sp = (m>=thr)?thr:0; out[t]=sp; mem=m-sp.
//
// Pure HBM-streaming (268 MB traffic, zero reuse). Findings:
//   R0: one-shot 4096x256, plain LDG/STG, front-batched loads -> 37.5us ncu
//   R1: persistent grid-stride -> 53.6us (MLP collapse; REJECTED)
//   R2: .cs evict-first hints  -> 45.6us (L1tex overhead; REJECTED)
//   R3: 512x2048 CTA shape     -> 36.8us, 7.3 TB/s e2e (WIN, current base)
//   R4: store-in-scan variant  -> (infra failure, no data; resubmitting unchanged)
// R5 == R4: interleave stores into the scan (store[t] issues right after step t,
// while v[t+1..7] are still in flight) -> overlap write drain with read shadow.

#ifndef IF_T
#define IF_T 8
#endif

__global__ __launch_bounds__(512, 4)
void if_scan_kernel(const float4* __restrict__ x,
                    const float* __restrict__ thresh,
                    float4* __restrict__ out,
                    int stride_vec)
{
    const int n = blockIdx.x * blockDim.x + threadIdx.x;  // exact cover: grid*block == n_vec

    const float thr = __ldg(thresh);

    // Front-batch all T independent loads (MLP=8, 128B in flight per thread)
    float4 v[IF_T];
#pragma unroll
    for (int t = 0; t < IF_T; ++t)
        v[t] = x[(size_t)t * stride_vec + n];

    float mx = 0.5f * thr, my = 0.5f * thr, mz = 0.5f * thr, mw = 0.5f * thr;

    // Scan with per-step store: out[t] leaves as soon as v[t] has arrived and
    // the 12-op ALU chain for step t is done; later loads still outstanding.
#pragma unroll
    for (int t = 0; t < IF_T; ++t) {
        mx += v[t].x; my += v[t].y; mz += v[t].z; mw += v[t].w;
        float sx = (mx >= thr) ? thr : 0.0f;
        float sy = (my >= thr) ? thr : 0.0f;
        float sz = (mz >= thr) ? thr : 0.0f;
        float sw = (mw >= thr) ? thr : 0.0f;
        float4 sp; sp.x = sx; sp.y = sy; sp.z = sz; sp.w = sw;
        out[(size_t)t * stride_vec + n] = sp;
        mx -= sx; my -= sy; mz -= sz; mw -= sw;
    }
}

extern "C" void kernel_launch(void* const* d_in, const int* in_sizes, int n_in,
                              void* d_out, int out_size)
{
    const float* x      = (const float*)d_in[0];
    const float* thresh = (const float*)d_in[1];
    float* out          = (float*)d_out;

    const int total = in_sizes[0];          // T*B*C*H*W = 33,554,432
    const int stride = total / IF_T;        // per-timestep elements = 4,194,304
    const int stride_vec = stride / 4;      // float4 units = 1,048,576 = 2^20

    const int threads = 512;
    const int blocks = stride_vec / threads;  // 2048, exact cover

    if_scan_kernel<<<blocks, threads>>>((const float4*)x, thresh,
                                        (float4*)out, stride_vec);
}